// round 5
// baseline (speedup 1.0000x reference)
#include <cuda_runtime.h>

// ColorQuantizer: out[pix] = PALETTE[argmin_j | relu(x@W1+b1)@W2+b2 - c_j |^2]
// Straight-through estimator output == hard palette lookup; softmax/sqrt drop out.
//
// f32x2 packed FFMA (fma.rn.f32x2) for the MLP, 2 pixels per lane-pair,
// 8 pixels per thread, weights pre-duplicated {w,w} so packed operands need no MOVs,
// b2 folded into the packed accumulators' init.
//
// R4 fix: sB2 was only 2/3 initialized (b2z pair was garbage) -> rel_err 0.82.

#define HW    262144u      // 512*512
#define PXT   8u           // pixels per thread
#define NTHR  (32u * HW / PXT)   // 1,048,576 threads
typedef unsigned long long ULL;

#define PV(v) ((float)(v) / 255.0f * 2.0f - 1.0f)
#define P3(a,b,c) {PV(a), PV(b), PV(c)}
static __device__ constexpr float PAL[16][3] = {
    P3(0,0,0),       P3(255,255,255), P3(255,0,0),     P3(0,255,0),
    P3(0,0,255),     P3(255,255,0),   P3(255,0,255),   P3(0,255,255),
    P3(128,128,128), P3(128,0,0),     P3(0,128,0),     P3(0,0,128),
    P3(128,128,0),   P3(128,0,128),   P3(0,128,128),   P3(192,192,192)
};

// Per hidden unit k, 8 duplicated pairs (16 floats, 64B):
//  {W1[0][k]}x2 {W1[1][k]}x2 {W1[2][k]}x2 {b1[k]}x2 {W2[k][0]}x2 {W2[k][1]}x2 {W2[k][2]}x2 {0}x2
__device__ float g_wp[32 * 16];
__device__ float g_b2p[8];       // {b2x,b2x, b2y,b2y, b2z,b2z, 0,0}

__global__ void prep_kernel(const float* __restrict__ W1, const float* __restrict__ b1,
                            const float* __restrict__ W2, const float* __restrict__ b2) {
    int k = threadIdx.x;
    if (k < 32) {
        float* w = &g_wp[k * 16];
        w[0]  = w[1]  = W1[0 * 32 + k];
        w[2]  = w[3]  = W1[1 * 32 + k];
        w[4]  = w[5]  = W1[2 * 32 + k];
        w[6]  = w[7]  = b1[k];
        w[8]  = w[9]  = W2[k * 3 + 0];
        w[10] = w[11] = W2[k * 3 + 1];
        w[12] = w[13] = W2[k * 3 + 2];
        w[14] = w[15] = 0.0f;
    }
    if (k < 3) { g_b2p[2 * k] = b2[k]; g_b2p[2 * k + 1] = b2[k]; }
    if (k == 3) { g_b2p[6] = 0.0f; g_b2p[7] = 0.0f; }
}

__device__ __forceinline__ ULL fma2(ULL a, ULL b, ULL c) {
    ULL d;
    asm("fma.rn.f32x2 %0, %1, %2, %3;" : "=l"(d) : "l"(a), "l"(b), "l"(c));
    return d;
}
__device__ __forceinline__ void unpk(ULL v, float& lo, float& hi) {
    asm("mov.b64 {%0, %1}, %2;" : "=f"(lo), "=f"(hi) : "l"(v));
}
__device__ __forceinline__ ULL pk(float lo, float hi) {
    ULL v;
    asm("mov.b64 %0, {%1, %2};" : "=l"(v) : "f"(lo), "f"(hi));
    return v;
}

__global__ __launch_bounds__(256) void cq_kernel(const float* __restrict__ x,
                                                 float* __restrict__ out) {
    __shared__ ULL    sW[32 * 8];     // duplicated weight pairs
    __shared__ ULL    sB2[4];
    __shared__ float4 spal4[16];      // palette as float4 for 1-LDS gather

    int tid = threadIdx.x;
    if (tid < 128) {
        reinterpret_cast<float4*>(sW)[tid] = reinterpret_cast<const float4*>(g_wp)[tid];
    }
    if (tid >= 128 && tid < 144) {
        int j = tid - 128;
        spal4[j] = make_float4(PAL[j][0], PAL[j][1], PAL[j][2], 0.0f);
    }
    if (tid >= 144 && tid < 148) {                     // FIX: all 4 ULLs (was 2)
        sB2[tid - 144] = reinterpret_cast<const ULL*>(g_b2p)[tid - 144];
    }
    __syncthreads();

    unsigned idx = blockIdx.x * 256u + tid;     // 8-pixel group index
    unsigned b   = idx >> 15;                   // batch (HW/8 = 32768 groups)
    unsigned r   = (idx & 32767u) << 3;         // pixel offset within plane

    const ULL* p0 = reinterpret_cast<const ULL*>(x + (size_t)b * 3 * HW + r);
    const ULL* p1 = reinterpret_cast<const ULL*>(x + (size_t)b * 3 * HW + HW + r);
    const ULL* p2 = reinterpret_cast<const ULL*>(x + (size_t)b * 3 * HW + 2 * HW + r);

    // 4 pairs per channel = 8 pixels, loaded as 128-bit (two aligned pairs each)
    ULL X0[4], X1[4], X2[4];
    {
        ulonglong2 t;
        t = reinterpret_cast<const ulonglong2*>(p0)[0]; X0[0] = t.x; X0[1] = t.y;
        t = reinterpret_cast<const ulonglong2*>(p0)[1]; X0[2] = t.x; X0[3] = t.y;
        t = reinterpret_cast<const ulonglong2*>(p1)[0]; X1[0] = t.x; X1[1] = t.y;
        t = reinterpret_cast<const ulonglong2*>(p1)[1]; X1[2] = t.x; X1[3] = t.y;
        t = reinterpret_cast<const ulonglong2*>(p2)[0]; X2[0] = t.x; X2[1] = t.y;
        t = reinterpret_cast<const ulonglong2*>(p2)[1]; X2[2] = t.x; X2[3] = t.y;
    }

    // Accumulators init with packed b2 (folds the bias add)
    ULL b2x = sB2[0], b2y = sB2[1], b2z = sB2[2];
    ULL P0[4] = {b2x, b2x, b2x, b2x};
    ULL P1[4] = {b2y, b2y, b2y, b2y};
    ULL P2[4] = {b2z, b2z, b2z, b2z};

    #pragma unroll 8
    for (int k = 0; k < 32; k++) {
        const ULL* wk = &sW[k * 8];
        ULL wx = wk[0], wy = wk[1], wz = wk[2], wb = wk[3];
        ULL u0 = wk[4], u1 = wk[5], u2 = wk[6];
        #pragma unroll
        for (int i = 0; i < 4; i++) {
            ULL a = fma2(X0[i], wx, fma2(X1[i], wy, fma2(X2[i], wz, wb)));
            float al, ah;
            unpk(a, al, ah);
            ULL h = pk(fmaxf(al, 0.0f), fmaxf(ah, 0.0f));   // relu on halves
            P0[i] = fma2(h, u0, P0[i]);
            P1[i] = fma2(h, u1, P1[i]);
            P2[i] = fma2(h, u2, P2[i]);
        }
    }

    float r0[PXT], r1[PXT], r2[PXT];
    #pragma unroll
    for (int i = 0; i < 4; i++) {
        float q0[2], q1[2], q2[2];
        unpk(P0[i], q0[0], q0[1]);
        unpk(P1[i], q1[0], q1[1]);
        unpk(P2[i], q2[0], q2[1]);
        #pragma unroll
        for (int hhalf = 0; hhalf < 2; hhalf++) {
            int   bi   = 0;
            float best = 3.4e38f;
            // argmin_j (-2 p.c_j + |c_j|^2); palette consts fold to FFMA immediates (rt=1)
            #pragma unroll
            for (int j = 0; j < 16; j++) {
                const float m0  = -2.0f * PAL[j][0];
                const float m1  = -2.0f * PAL[j][1];
                const float m2  = -2.0f * PAL[j][2];
                const float csq = PAL[j][0] * PAL[j][0] + PAL[j][1] * PAL[j][1]
                                + PAL[j][2] * PAL[j][2];
                float s = fmaf(q0[hhalf], m0, fmaf(q1[hhalf], m1, fmaf(q2[hhalf], m2, csq)));
                if (s < best) { best = s; bi = j; }         // strict <: first-index ties
            }
            float4 col = spal4[bi];
            int p = 2 * i + hhalf;
            r0[p] = col.x; r1[p] = col.y; r2[p] = col.z;
        }
    }

    float* o0 = out + (size_t)b * 3 * HW + r;
    reinterpret_cast<float4*>(o0)[0]            = make_float4(r0[0], r0[1], r0[2], r0[3]);
    reinterpret_cast<float4*>(o0)[1]            = make_float4(r0[4], r0[5], r0[6], r0[7]);
    reinterpret_cast<float4*>(o0 + HW)[0]       = make_float4(r1[0], r1[1], r1[2], r1[3]);
    reinterpret_cast<float4*>(o0 + HW)[1]       = make_float4(r1[4], r1[5], r1[6], r1[7]);
    reinterpret_cast<float4*>(o0 + 2 * HW)[0]   = make_float4(r2[0], r2[1], r2[2], r2[3]);
    reinterpret_cast<float4*>(o0 + 2 * HW)[1]   = make_float4(r2[4], r2[5], r2[6], r2[7]);
}

extern "C" void kernel_launch(void* const* d_in, const int* in_sizes, int n_in,
                              void* d_out, int out_size) {
    const float* x  = (const float*)d_in[0];
    const float* W1 = (const float*)d_in[1];
    const float* b1 = (const float*)d_in[2];
    const float* W2 = (const float*)d_in[3];
    const float* b2 = (const float*)d_in[4];
    float* out = (float*)d_out;

    prep_kernel<<<1, 32>>>(W1, b1, W2, b2);
    cq_kernel<<<NTHR / 256, 256>>>(x, out);
}